// round 11
// baseline (speedup 1.0000x reference)
#include <cuda_runtime.h>
#include <cuda_fp16.h>
#include <math.h>

#define BQ 2
#define CQ 80
#define HQ 32
#define WQ 88
#define NPTS 262144            // 128*128*16 points per batch
#define PTS_PER_BLK 128
#define THREADS 320
#define NG4 20                 // 80 channels = 20 groups of 4
#define NSLOT 45               // x-pair slots per phase (covers x0 in [-1,87])
#define PROW 24                // pair-row stride in uint4 (384B = 3 lines exactly)
#define SROWU 64               // staging row stride in 32b words (256B, 0 mod 32 banks)
#define ITEMSB (PTS_PER_BLK * NG4)   // 2560 gather items per block

// Pair-interleaved fp16 features: [b][phase][y][slot][g4] -> uint4 =
// {pix0.c01, pix0.c23, pix1.c01, pix1.c23} for channels 4*g4..4*g4+3.
// phase p, slot s covers pixels x = (2s-p, 2s-p+1); out-of-range x zero-padded.
__device__ uint4 g_pair[BQ * 2 * HQ * NSLOT * PROW];
// Combined 3x4 projection matrix per batch: F = (intr*scale) * extr * bda
__device__ float g_F[BQ][12];

static __device__ __forceinline__ unsigned h2bits(__half2 h) {
    return *reinterpret_cast<unsigned*>(&h);
}

// ---------------- prep: build pair planes + matrices ----------------
// grid (HQ, BQ), 256 threads. Each block handles one (b, y) image row.
__global__ void prep_kernel(const float* __restrict__ feat,
                            const float* __restrict__ intrin,
                            const float* __restrict__ extrin,
                            const float* __restrict__ bda) {
    __shared__ float tile[CQ][WQ];   // 80x88 f32 = 28.2KB
    int y = blockIdx.x;
    int b = blockIdx.y;
    int tid = threadIdx.x;

    if (blockIdx.x == 0 && blockIdx.y == 0 && tid < BQ) {
        int bb = tid;
        const float* In = intrin + bb * 16;
        const float* Ex = extrin + bb * 16;
        const float* Bd = bda + bb * 16;
        float P[3][4];
        for (int r = 0; r < 3; r++) {
            float s = (r < 2) ? 0.125f : 1.0f;
            for (int cc = 0; cc < 4; cc++) {
                float acc = 0.0f;
                for (int k = 0; k < 3; k++)
                    acc += In[r * 4 + k] * s * Ex[k * 4 + cc];
                P[r][cc] = acc;
            }
        }
        for (int r = 0; r < 3; r++)
            for (int cc = 0; cc < 4; cc++) {
                float acc = 0.0f;
                for (int k = 0; k < 4; k++)
                    acc += P[r][k] * Bd[k * 4 + cc];
                g_F[bb][r * 4 + cc] = acc;
            }
    }

    for (int idx = tid; idx < CQ * WQ; idx += 256) {
        int c = idx / WQ;
        int x = idx - c * WQ;
        tile[c][x] = feat[((size_t)(b * CQ + c) * HQ + y) * WQ + x];
    }
    __syncthreads();

    for (int j = tid; j < 2 * NSLOT * NG4; j += 256) {
        int phase = j / (NSLOT * NG4);
        int rest = j - phase * (NSLOT * NG4);
        int slot = rest / NG4;
        int g4 = rest - slot * NG4;
        int xa = 2 * slot - phase;
        int xb = xa + 1;
        int c0 = 4 * g4;
        float a0 = 0.f, a1 = 0.f, a2 = 0.f, a3 = 0.f;
        float b0 = 0.f, b1 = 0.f, b2 = 0.f, b3 = 0.f;
        if (xa >= 0 && xa < WQ) {
            a0 = tile[c0][xa]; a1 = tile[c0 + 1][xa];
            a2 = tile[c0 + 2][xa]; a3 = tile[c0 + 3][xa];
        }
        if (xb >= 0 && xb < WQ) {
            b0 = tile[c0][xb]; b1 = tile[c0 + 1][xb];
            b2 = tile[c0 + 2][xb]; b3 = tile[c0 + 3][xb];
        }
        uint4 v;
        v.x = h2bits(__floats2half2_rn(a0, a1));
        v.y = h2bits(__floats2half2_rn(a2, a3));
        v.z = h2bits(__floats2half2_rn(b0, b1));
        v.w = h2bits(__floats2half2_rn(b2, b3));
        size_t ridx = ((size_t)((b * 2 + phase) * HQ + y) * NSLOT + slot) * PROW + g4;
        g_pair[ridx] = v;
    }
}

// ---------------- main kernel ----------------
__global__ void __launch_bounds__(THREADS, 4)
bev_kernel(float* __restrict__ out) {
    __shared__ uint4 s_wh[PTS_PER_BLK];             // half2 weights {w0,w1,w2,w3}
    __shared__ int2  s_row[PTS_PER_BLK];            // uint4 row bases {y0-row, y1-row}
    __shared__ unsigned s_stg[PTS_PER_BLK * SROWU]; // 128 rows x 40 used words, swizzled

    const int bidx = blockIdx.x;
    const int b = bidx >> 11;                 // 2048 blocks per batch
    const int nbase = (bidx & 2047) * PTS_PER_BLK;
    const int tid = threadIdx.x;

    // ---- Phase A: geometry for 128 points ----
    if (tid < PTS_PER_BLK) {
        int n = nbase + tid;
        int ix = n >> 11;            // NY*NZ = 2048
        int iy = (n >> 4) & 127;     // NZ = 16
        int iz = n & 15;
        float X = -51.2f + ix * 0.8f;
        float Y = -51.2f + iy * 0.8f;
        float Z = -5.0f + iz * 0.5f;
        const float* F = g_F[b];
        float px = F[0] * X + F[1] * Y + F[2]  * Z + F[3];
        float py = F[4] * X + F[5] * Y + F[6]  * Z + F[7];
        float pz = F[8] * X + F[9] * Y + F[10] * Z + F[11];
        float u = px / pz;
        float v = py / pz;
        u = u / (float)WQ * 2.0f - 1.0f;
        v = v / (float)HQ * 2.0f - 1.0f;
        float x = (u + 1.0f) * 0.5f * (float)(WQ - 1);
        float y = (v + 1.0f) * 0.5f * (float)(HQ - 1);
        if (!(isfinite(x) && isfinite(y))) { x = -10.0f; y = -10.0f; }
        float x0f = floorf(x), y0f = floorf(y);
        float wx1 = x - x0f, wy1 = y - y0f;
        float wx0 = 1.0f - wx1, wy0 = 1.0f - wy1;
        float x1f = x0f + 1.0f, y1f = y0f + 1.0f;
        bool vx0 = (x0f >= 0.0f) && (x0f <= (float)(WQ - 1));
        bool vx1 = (x1f >= 0.0f) && (x1f <= (float)(WQ - 1));
        bool vy0 = (y0f >= 0.0f) && (y0f <= (float)(HQ - 1));
        bool vy1 = (y1f >= 0.0f) && (y1f <= (float)(HQ - 1));
        // pair slot addressing: element0 = x0, element1 = x0+1
        int x0i = (int)x0f;                       // saturating cvt
        x0i = min(max(x0i, -1), WQ - 1);
        int phase = x0i & 1;                      // -1 -> 1
        int slot = (x0i + 1) >> 1;                // [-1,87] -> [0,44]
        int yi0 = (int)fminf(fmaxf(y0f, 0.0f), (float)(HQ - 1));
        int yi1 = (int)fminf(fmaxf(y1f, 0.0f), (float)(HQ - 1));
        int pb = (b * 2 + phase) * HQ;
        s_row[tid] = make_int2(((pb + yi0) * NSLOT + slot) * PROW,
                               ((pb + yi1) * NSLOT + slot) * PROW);
        float w0 = (vx0 && vy0) ? wx0 * wy0 : 0.0f;   // y0 row, element0
        float w1 = (vx1 && vy0) ? wx1 * wy0 : 0.0f;   // y0 row, element1
        float w2 = (vx0 && vy1) ? wx0 * wy1 : 0.0f;   // y1 row, element0
        float w3 = (vx1 && vy1) ? wx1 * wy1 : 0.0f;   // y1 row, element1
        uint4 wh;
        wh.x = h2bits(__float2half2_rn(w0));
        wh.y = h2bits(__float2half2_rn(w1));
        wh.z = h2bits(__float2half2_rn(w2));
        wh.w = h2bits(__float2half2_rn(w3));
        s_wh[tid] = wh;
    }
    __syncthreads();

    // ---- Phase B: pair-row gathers (2 LDG.128/point-group) + HFMA2 -> fp16 staging ----
    // Staging word for channel-pair cp at point p: p*64 + 4*((cp>>2)^(p4&7)) + (cp&3).
    const uint4* gp = g_pair;
    #pragma unroll
    for (int u = 0; u < ITEMSB / THREADS; u++) {   // 8
        int i = u * THREADS + tid;
        int p = i / NG4;
        int g4 = i - p * NG4;
        uint4 wh = s_wh[p];
        int2 rw = s_row[p];
        __half2 acc01 = __float2half2_rn(0.f);
        __half2 acc23 = acc01;
        if ((wh.x | wh.y) != 0u) {
            uint4 raw = __ldg(&gp[rw.x + g4]);
            __half2 w0 = *reinterpret_cast<__half2*>(&wh.x);
            __half2 w1 = *reinterpret_cast<__half2*>(&wh.y);
            acc01 = __hfma2(w0, *reinterpret_cast<__half2*>(&raw.x), acc01);
            acc01 = __hfma2(w1, *reinterpret_cast<__half2*>(&raw.z), acc01);
            acc23 = __hfma2(w0, *reinterpret_cast<__half2*>(&raw.y), acc23);
            acc23 = __hfma2(w1, *reinterpret_cast<__half2*>(&raw.w), acc23);
        }
        if ((wh.z | wh.w) != 0u) {
            uint4 raw = __ldg(&gp[rw.y + g4]);
            __half2 w2 = *reinterpret_cast<__half2*>(&wh.z);
            __half2 w3 = *reinterpret_cast<__half2*>(&wh.w);
            acc01 = __hfma2(w2, *reinterpret_cast<__half2*>(&raw.x), acc01);
            acc01 = __hfma2(w3, *reinterpret_cast<__half2*>(&raw.z), acc01);
            acc23 = __hfma2(w2, *reinterpret_cast<__half2*>(&raw.y), acc23);
            acc23 = __hfma2(w3, *reinterpret_cast<__half2*>(&raw.w), acc23);
        }
        int p4 = p >> 2;
        int wbase = p * SROWU + 4 * ((g4 >> 1) ^ (p4 & 7)) + 2 * (g4 & 1);
        *reinterpret_cast<uint2*>(&s_stg[wbase]) =
            make_uint2(h2bits(acc01), h2bits(acc23));
    }
    __syncthreads();

    // ---- Phase C: conflict-free LDS.32 + coalesced STG.128 ----
    // Warp = 4 channel-pairs x 8 point-quads -> 32 distinct banks per LDS step.
    {
        float4* out4 = (float4*)out;
        const int w = tid >> 5;      // warp 0..9 -> cp block
        const int l = tid & 31;
        const int cp = w * 4 + (l >> 3);   // 0..39
        const int lp = l & 7;
        #pragma unroll
        for (int u = 0; u < 4; u++) {
            int p4 = u * 8 + lp;           // 0..31
            int word = 4 * (w ^ (p4 & 7)) + (l >> 3);
            int base = (4 * p4) * SROWU + word;
            unsigned u0 = s_stg[base + 0 * SROWU];
            unsigned u1 = s_stg[base + 1 * SROWU];
            unsigned u2 = s_stg[base + 2 * SROWU];
            unsigned u3 = s_stg[base + 3 * SROWU];
            float2 f0 = __half22float2(*reinterpret_cast<__half2*>(&u0));
            float2 f1 = __half22float2(*reinterpret_cast<__half2*>(&u1));
            float2 f2 = __half22float2(*reinterpret_cast<__half2*>(&u2));
            float2 f3 = __half22float2(*reinterpret_cast<__half2*>(&u3));
            int c0 = 2 * cp;
            size_t idx0 = (size_t)(b * CQ + c0) * (NPTS / 4) + (nbase >> 2) + p4;
            size_t idx1 = idx0 + (NPTS / 4);
            out4[idx0] = make_float4(f0.x, f1.x, f2.x, f3.x);
            out4[idx1] = make_float4(f0.y, f1.y, f2.y, f3.y);
        }
    }
}

extern "C" void kernel_launch(void* const* d_in, const int* in_sizes, int n_in,
                              void* d_out, int out_size) {
    const float* img_feats = (const float*)d_in[0];
    const float* intrin    = (const float*)d_in[1];
    const float* extrin    = (const float*)d_in[2];
    const float* bda       = (const float*)d_in[3];
    float* out = (float*)d_out;

    dim3 pgrid(HQ, BQ);
    prep_kernel<<<pgrid, 256>>>(img_feats, intrin, extrin, bda);

    int nblocks = BQ * (NPTS / PTS_PER_BLK);   // 4096
    bev_kernel<<<nblocks, THREADS>>>(out);
}

// round 12
// speedup vs baseline: 1.2381x; 1.2381x over previous
#include <cuda_runtime.h>
#include <cuda_fp16.h>
#include <math.h>

#define BQ 2
#define CQ 80
#define HQ 32
#define WQ 88
#define PIX (HQ * WQ)          // 2816 pixels
#define NPTS 262144            // 128*128*16 points per batch
#define PTS_PER_BLK 128
#define THREADS 320
#define NG8 10                 // 80 channels = 10 groups of 8 (uint4 of halves)
#define FROW 10                // feature row stride in uint4 (160B, unpadded)
#define ITEMS8 (PTS_PER_BLK * NG8)      // 1280 gather items per block
#define SROWU 64               // staging row stride in uints (16 uint4 = 256B, 0 mod 32 banks)

// Transposed features in fp16: (B, H*W, C), 8 channels per uint4, 10 uint4/pixel.
__device__ uint4 g_featTh[BQ * PIX * FROW];
// Combined 3x4 projection matrix per batch: F = (intr*scale) * extr * bda
__device__ float g_F[BQ][12];

// ---------------- prep: tiled transpose (B,C,HW) -> (B,HW,C) fp16 + matrices ----------------
__global__ void prep_kernel(const float* __restrict__ feat,
                            const float* __restrict__ intrin,
                            const float* __restrict__ extrin,
                            const float* __restrict__ bda) {
    __shared__ float tile[32][33];
    if (blockIdx.x == 0 && blockIdx.y == 0 && blockIdx.z == 0 &&
        threadIdx.y == 0 && threadIdx.x < BQ) {
        int b = threadIdx.x;
        const float* In = intrin + b * 16;
        const float* Ex = extrin + b * 16;
        const float* Bd = bda + b * 16;
        float P[3][4];
        for (int r = 0; r < 3; r++) {
            float s = (r < 2) ? 0.125f : 1.0f;
            for (int cc = 0; cc < 4; cc++) {
                float acc = 0.0f;
                for (int k = 0; k < 3; k++)
                    acc += In[r * 4 + k] * s * Ex[k * 4 + cc];
                P[r][cc] = acc;
            }
        }
        for (int r = 0; r < 3; r++)
            for (int cc = 0; cc < 4; cc++) {
                float acc = 0.0f;
                for (int k = 0; k < 4; k++)
                    acc += P[r][k] * Bd[k * 4 + cc];
                g_F[b][r * 4 + cc] = acc;
            }
    }
    int b = blockIdx.z;
    int ct = blockIdx.y * 32;
    int pt = blockIdx.x * 32;
    int tx = threadIdx.x, ty = threadIdx.y;   // (32,8)
    const float* src = feat + (size_t)b * CQ * PIX;
    #pragma unroll
    for (int j = 0; j < 32; j += 8) {
        int c = ct + ty + j;
        int p = pt + tx;
        if (c < CQ && p < PIX)
            tile[ty + j][tx] = src[(size_t)c * PIX + p];
    }
    __syncthreads();
    __half* dst = (__half*)g_featTh;
    dst += (size_t)b * PIX * CQ;
    #pragma unroll
    for (int j = 0; j < 32; j += 8) {
        int p = pt + ty + j;
        int c = ct + tx;
        if (c < CQ && p < PIX)
            dst[(size_t)p * CQ + c] = __float2half(tile[tx][ty + j]);
    }
}

// ---------------- main kernel ----------------
__global__ void __launch_bounds__(THREADS)
bev_kernel(float* __restrict__ out) {
    __shared__ uint4  s_wh[PTS_PER_BLK];                // 4 broadcast half2 weights
    __shared__ int4   s_idx4[PTS_PER_BLK];              // pixel * FROW (uint4 base)
    __shared__ uint4  s_stg[PTS_PER_BLK * (SROWU / 4)]; // 128 rows x 16 uint4 (fp16, swizzled)

    const int bidx = blockIdx.x;
    const int b = bidx >> 11;                 // 2048 blocks per batch
    const int nbase = (bidx & 2047) * PTS_PER_BLK;
    const int tid = threadIdx.x;

    // ---- Phase A: geometry for 128 points ----
    if (tid < PTS_PER_BLK) {
        int n = nbase + tid;
        int ix = n >> 11;            // NY*NZ = 2048
        int iy = (n >> 4) & 127;     // NZ = 16
        int iz = n & 15;
        float X = -51.2f + ix * 0.8f;
        float Y = -51.2f + iy * 0.8f;
        float Z = -5.0f + iz * 0.5f;
        const float* F = g_F[b];
        float px = F[0] * X + F[1] * Y + F[2]  * Z + F[3];
        float py = F[4] * X + F[5] * Y + F[6]  * Z + F[7];
        float pz = F[8] * X + F[9] * Y + F[10] * Z + F[11];
        float u = px / pz;
        float v = py / pz;
        u = u / (float)WQ * 2.0f - 1.0f;
        v = v / (float)HQ * 2.0f - 1.0f;
        float x = (u + 1.0f) * 0.5f * (float)(WQ - 1);
        float y = (v + 1.0f) * 0.5f * (float)(HQ - 1);
        if (!(isfinite(x) && isfinite(y))) { x = -10.0f; y = -10.0f; }
        float x0f = floorf(x), y0f = floorf(y);
        float wx1 = x - x0f, wy1 = y - y0f;
        float wx0 = 1.0f - wx1, wy0 = 1.0f - wy1;
        float x1f = x0f + 1.0f, y1f = y0f + 1.0f;
        bool vx0 = (x0f >= 0.0f) && (x0f <= (float)(WQ - 1));
        bool vx1 = (x1f >= 0.0f) && (x1f <= (float)(WQ - 1));
        bool vy0 = (y0f >= 0.0f) && (y0f <= (float)(HQ - 1));
        bool vy1 = (y1f >= 0.0f) && (y1f <= (float)(HQ - 1));
        int xi0 = (int)fminf(fmaxf(x0f, 0.0f), (float)(WQ - 1));
        int xi1 = (int)fminf(fmaxf(x1f, 0.0f), (float)(WQ - 1));
        int yi0 = (int)fminf(fmaxf(y0f, 0.0f), (float)(HQ - 1));
        int yi1 = (int)fminf(fmaxf(y1f, 0.0f), (float)(HQ - 1));
        int4 id;
        id.x = (yi0 * WQ + xi0) * FROW;
        id.y = (yi0 * WQ + xi1) * FROW;
        id.z = (yi1 * WQ + xi0) * FROW;
        id.w = (yi1 * WQ + xi1) * FROW;
        s_idx4[tid] = id;
        float w0 = (vx0 && vy0) ? wx0 * wy0 : 0.0f;
        float w1 = (vx1 && vy0) ? wx1 * wy0 : 0.0f;
        float w2 = (vx0 && vy1) ? wx0 * wy1 : 0.0f;
        float w3 = (vx1 && vy1) ? wx1 * wy1 : 0.0f;
        __half2 h0 = __float2half2_rn(w0);
        __half2 h1 = __float2half2_rn(w1);
        __half2 h2 = __float2half2_rn(w2);
        __half2 h3 = __float2half2_rn(w3);
        uint4 wh;
        wh.x = *reinterpret_cast<unsigned*>(&h0);
        wh.y = *reinterpret_cast<unsigned*>(&h1);
        wh.z = *reinterpret_cast<unsigned*>(&h2);
        wh.w = *reinterpret_cast<unsigned*>(&h3);
        s_wh[tid] = wh;
    }
    __syncthreads();

    // ---- Phase B: predicated fp16 LDG.128 gathers (8 ch) + HFMA2 combine -> fp16 staging ----
    // Store word-rotated by rx = p4>>3 (0..3) so Phase C is conflict-free.
    const uint4* fT = g_featTh + (size_t)b * PIX * FROW;
    #pragma unroll
    for (int it = 0; it < 4; it++) {
        int i = it * THREADS + tid;   // 0..1279
        int p = i / NG8;
        int g = i - p * NG8;
        uint4 wh = s_wh[p];
        int4 id = s_idx4[p];
        __half2 acc0 = __float2half2_rn(0.f);
        __half2 acc1 = acc0, acc2 = acc0, acc3 = acc0;
        #define CORNER(WU, IDK)                                              \
            if (WU != 0u) {                                                  \
                uint4 raw = __ldg(&fT[IDK + g]);                             \
                __half2 wk = *reinterpret_cast<__half2*>(&WU);               \
                acc0 = __hfma2(wk, *reinterpret_cast<__half2*>(&raw.x), acc0); \
                acc1 = __hfma2(wk, *reinterpret_cast<__half2*>(&raw.y), acc1); \
                acc2 = __hfma2(wk, *reinterpret_cast<__half2*>(&raw.z), acc2); \
                acc3 = __hfma2(wk, *reinterpret_cast<__half2*>(&raw.w), acc3); \
            }
        CORNER(wh.x, id.x)
        CORNER(wh.y, id.y)
        CORNER(wh.z, id.z)
        CORNER(wh.w, id.w)
        #undef CORNER
        uint4 st;
        st.x = *reinterpret_cast<unsigned*>(&acc0);
        st.y = *reinterpret_cast<unsigned*>(&acc1);
        st.z = *reinterpret_cast<unsigned*>(&acc2);
        st.w = *reinterpret_cast<unsigned*>(&acc3);
        int p4 = p >> 2;
        int G = p4 & 7;
        int rx = p4 >> 3;             // 0..3: rotate words right by rx
        uint4 r = st;
        if (rx == 1) r = make_uint4(st.w, st.x, st.y, st.z);
        else if (rx == 2) r = make_uint4(st.z, st.w, st.x, st.y);
        else if (rx == 3) r = make_uint4(st.y, st.z, st.w, st.x);
        s_stg[p * (SROWU / 4) + (g ^ G)] = r;
    }
    __syncthreads();

    // ---- Phase C: conflict-free LDS.32 (half2 = channel pair) + 2x coalesced STG.128 ----
    {
        const unsigned* s_u = (const unsigned*)s_stg;
        float4* out4 = (float4*)out;
        #pragma unroll
        for (int it = 0; it < 4; it++) {
            int i = it * THREADS + tid;   // 0..1279
            int cp = i >> 5;              // channel-pair 0..39
            int p4 = i & 31;              // point-quad 0..31
            int G = p4 & 7;
            int rx = p4 >> 3;             // 0..3
            int word = 4 * ((cp >> 2) ^ G) + ((cp + rx) & 3);
            int base = (4 * p4) * SROWU + word;
            unsigned u0 = s_u[base + 0 * SROWU];
            unsigned u1 = s_u[base + 1 * SROWU];
            unsigned u2 = s_u[base + 2 * SROWU];
            unsigned u3 = s_u[base + 3 * SROWU];
            float2 f0 = __half22float2(*reinterpret_cast<__half2*>(&u0));
            float2 f1 = __half22float2(*reinterpret_cast<__half2*>(&u1));
            float2 f2 = __half22float2(*reinterpret_cast<__half2*>(&u2));
            float2 f3 = __half22float2(*reinterpret_cast<__half2*>(&u3));
            int c0 = 2 * cp;
            size_t idx0 = (size_t)(b * CQ + c0) * (NPTS / 4) + (nbase >> 2) + p4;
            size_t idx1 = idx0 + (NPTS / 4);
            out4[idx0] = make_float4(f0.x, f1.x, f2.x, f3.x);
            out4[idx1] = make_float4(f0.y, f1.y, f2.y, f3.y);
        }
    }
}

extern "C" void kernel_launch(void* const* d_in, const int* in_sizes, int n_in,
                              void* d_out, int out_size) {
    const float* img_feats = (const float*)d_in[0];
    const float* intrin    = (const float*)d_in[1];
    const float* extrin    = (const float*)d_in[2];
    const float* bda       = (const float*)d_in[3];
    float* out = (float*)d_out;

    dim3 tgrid((PIX + 31) / 32, (CQ + 31) / 32, BQ);
    prep_kernel<<<tgrid, dim3(32, 8)>>>(img_feats, intrin, extrin, bda);

    int nblocks = BQ * (NPTS / PTS_PER_BLK);   // 4096
    bev_kernel<<<nblocks, THREADS>>>(out);
}